// round 1
// baseline (speedup 1.0000x reference)
#include <cuda_runtime.h>
#include <math.h>

#define SQ   2048   // sequence length
#define DM   2048   // d_model
#define DH   128    // d_head
#define NH   16     // num heads
#define DL   512    // d_latent
#define BB   4      // batch
#define MTOT (BB*SQ) // 8192 total rows

// ---------------- scratch (static device allocations; no cudaMalloc allowed) ----
__device__ float g_lat[MTOT * DL];                       // 16 MB
__device__ float g_key[MTOT * DM];                       // 64 MB
__device__ float g_val[MTOT * DM];                       // 64 MB
__device__ float g_q[MTOT * DM];                         // 64 MB
__device__ float g_ctx[MTOT * DM];                       // 64 MB
__device__ float g_scores[(size_t)BB * NH * SQ * SQ];    // 1.07 GB

// ---------------- generic tiled fp32 GEMM --------------------------------------
// C[M,N] = scale * (A @ B(^T if BT)) + bias
// A: [M,K] row-major, lda
// B: NN -> [K,N] row-major ldb ; NT -> [N,K] row-major ldb
// Batched over blockIdx.z: offset = (z/nInner)*Out + (z%nInner)*In per operand.
// Requires M%64==0, N%64==0, K%16==0 (true for all calls here).
template<bool BT>
__launch_bounds__(256)
__global__ void gemm_kernel(const float* __restrict__ A, const float* __restrict__ B,
                            float* __restrict__ C, const float* __restrict__ bias,
                            int M, int N, int K, int lda, int ldb, int ldc,
                            int nInner,
                            long long aOut, long long aIn,
                            long long bOut, long long bIn,
                            long long cOut, long long cIn,
                            float scale)
{
    __shared__ float As[16][68];   // [k][m], padded
    __shared__ float Bs[16][68];   // [k][n], padded

    const int z  = blockIdx.z;
    const int zo = z / nInner;
    const int zi = z % nInner;
    A += zo * aOut + zi * aIn;
    B += zo * bOut + zi * bIn;
    C += zo * cOut + zi * cIn;

    const int m0 = blockIdx.y * 64;
    const int n0 = blockIdx.x * 64;
    const int tid = threadIdx.x;
    const int tx = tid & 15;       // col group
    const int ty = tid >> 4;       // row group

    // A-load mapping: 64 rows x 4 float4 segments
    const int lr = tid >> 2;       // 0..63
    const int ls = tid & 3;        // 0..3
    // NN B-load mapping: 16 rows x 16 float4 segments
    const int br = tid >> 4;       // 0..15
    const int bs = tid & 15;       // 0..15

    float acc[4][4];
#pragma unroll
    for (int i = 0; i < 4; i++)
#pragma unroll
        for (int j = 0; j < 4; j++) acc[i][j] = 0.0f;

    for (int k0 = 0; k0 < K; k0 += 16) {
        // load A tile [64 x 16] -> As[k][m] (transposed)
        {
            float4 av = *(const float4*)(A + (long long)(m0 + lr) * lda + k0 + ls * 4);
            As[ls * 4 + 0][lr] = av.x;
            As[ls * 4 + 1][lr] = av.y;
            As[ls * 4 + 2][lr] = av.z;
            As[ls * 4 + 3][lr] = av.w;
        }
        if (BT) {
            // B tile rows are the N dim: [64 x 16] -> Bs[k][n] (transposed)
            float4 bv = *(const float4*)(B + (long long)(n0 + lr) * ldb + k0 + ls * 4);
            Bs[ls * 4 + 0][lr] = bv.x;
            Bs[ls * 4 + 1][lr] = bv.y;
            Bs[ls * 4 + 2][lr] = bv.z;
            Bs[ls * 4 + 3][lr] = bv.w;
        } else {
            // B tile [16 x 64] -> Bs[k][n] direct
            float4 bv = *(const float4*)(B + (long long)(k0 + br) * ldb + n0 + bs * 4);
            *(float4*)&Bs[br][bs * 4] = bv;
        }
        __syncthreads();

#pragma unroll
        for (int k = 0; k < 16; k++) {
            float4 a = *(const float4*)&As[k][ty * 4];
            float4 b = *(const float4*)&Bs[k][tx * 4];
            acc[0][0] += a.x * b.x; acc[0][1] += a.x * b.y; acc[0][2] += a.x * b.z; acc[0][3] += a.x * b.w;
            acc[1][0] += a.y * b.x; acc[1][1] += a.y * b.y; acc[1][2] += a.y * b.z; acc[1][3] += a.y * b.w;
            acc[2][0] += a.z * b.x; acc[2][1] += a.z * b.y; acc[2][2] += a.z * b.z; acc[2][3] += a.z * b.w;
            acc[3][0] += a.w * b.x; acc[3][1] += a.w * b.y; acc[3][2] += a.w * b.z; acc[3][3] += a.w * b.w;
        }
        __syncthreads();
    }

    float bvv[4] = {0.f, 0.f, 0.f, 0.f};
    if (bias) {
#pragma unroll
        for (int j = 0; j < 4; j++) bvv[j] = bias[n0 + tx * 4 + j];
    }
#pragma unroll
    for (int i = 0; i < 4; i++) {
        long long row = (long long)(m0 + ty * 4 + i) * ldc;
#pragma unroll
        for (int j = 0; j < 4; j++) {
            C[row + n0 + tx * 4 + j] = acc[i][j] * scale + bvv[j];
        }
    }
}

// ---------------- row softmax over last dim (row length SQ=2048) ----------------
__launch_bounds__(256)
__global__ void softmax_kernel(float* __restrict__ P)
{
    const long long row = blockIdx.x;
    float* p = P + row * SQ;
    const int tid = threadIdx.x;   // 256 threads, 8 floats each (2 x float4)

    float4 v1 = ((const float4*)p)[tid];
    float4 v2 = ((const float4*)p)[256 + tid];

    float m = fmaxf(fmaxf(fmaxf(v1.x, v1.y), fmaxf(v1.z, v1.w)),
                    fmaxf(fmaxf(v2.x, v2.y), fmaxf(v2.z, v2.w)));

    __shared__ float red[256];
    red[tid] = m;
    __syncthreads();
    for (int s = 128; s > 0; s >>= 1) {
        if (tid < s) red[tid] = fmaxf(red[tid], red[tid + s]);
        __syncthreads();
    }
    const float rowmax = red[0];
    __syncthreads();

    v1.x = __expf(v1.x - rowmax); v1.y = __expf(v1.y - rowmax);
    v1.z = __expf(v1.z - rowmax); v1.w = __expf(v1.w - rowmax);
    v2.x = __expf(v2.x - rowmax); v2.y = __expf(v2.y - rowmax);
    v2.z = __expf(v2.z - rowmax); v2.w = __expf(v2.w - rowmax);

    float s8 = (v1.x + v1.y) + (v1.z + v1.w) + (v2.x + v2.y) + (v2.z + v2.w);
    red[tid] = s8;
    __syncthreads();
    for (int s = 128; s > 0; s >>= 1) {
        if (tid < s) red[tid] += red[tid + s];
        __syncthreads();
    }
    const float inv = 1.0f / red[0];

    v1.x *= inv; v1.y *= inv; v1.z *= inv; v1.w *= inv;
    v2.x *= inv; v2.y *= inv; v2.z *= inv; v2.w *= inv;
    ((float4*)p)[tid] = v1;
    ((float4*)p)[256 + tid] = v2;
}

// ---------------- launch -------------------------------------------------------
extern "C" void kernel_launch(void* const* d_in, const int* in_sizes, int n_in,
                              void* d_out, int out_size)
{
    const float* x      = (const float*)d_in[0];
    const float* W_down = (const float*)d_in[1];
    const float* b_down = (const float*)d_in[2];
    const float* W_uk   = (const float*)d_in[3];
    const float* b_uk   = (const float*)d_in[4];
    const float* W_uv   = (const float*)d_in[5];
    const float* b_uv   = (const float*)d_in[6];
    const float* W_q    = (const float*)d_in[7];
    const float* b_q    = (const float*)d_in[8];
    const float* W_o    = (const float*)d_in[9];
    const float* b_o    = (const float*)d_in[10];
    float* out = (float*)d_out;

    void *p_lat, *p_key, *p_val, *p_q, *p_ctx, *p_sc;
    cudaGetSymbolAddress(&p_lat, g_lat);
    cudaGetSymbolAddress(&p_key, g_key);
    cudaGetSymbolAddress(&p_val, g_val);
    cudaGetSymbolAddress(&p_q,   g_q);
    cudaGetSymbolAddress(&p_ctx, g_ctx);
    cudaGetSymbolAddress(&p_sc,  g_scores);
    float* lat = (float*)p_lat;
    float* key = (float*)p_key;
    float* val = (float*)p_val;
    float* q   = (float*)p_q;
    float* ctx = (float*)p_ctx;
    float* sc  = (float*)p_sc;

    dim3 blk(256);
    const float inv_sqrt_dh = 0.08838834764831845f; // 1/sqrt(128)

    // 1) latents = x @ W_down + b_down        [8192, 512]
    gemm_kernel<false><<<dim3(DL/64, MTOT/64, 1), blk>>>(
        x, W_down, lat, b_down, MTOT, DL, DM, DM, DL, DL,
        1, 0, 0, 0, 0, 0, 0, 1.0f);

    // 2) keys = latents @ W_uk + b_uk         [8192, 2048]
    gemm_kernel<false><<<dim3(DM/64, MTOT/64, 1), blk>>>(
        lat, W_uk, key, b_uk, MTOT, DM, DL, DL, DM, DM,
        1, 0, 0, 0, 0, 0, 0, 1.0f);

    // 3) values = latents @ W_uv + b_uv       [8192, 2048]
    gemm_kernel<false><<<dim3(DM/64, MTOT/64, 1), blk>>>(
        lat, W_uv, val, b_uv, MTOT, DM, DL, DL, DM, DM,
        1, 0, 0, 0, 0, 0, 0, 1.0f);

    // 4) q = x @ W_q + b_q                    [8192, 2048]
    gemm_kernel<false><<<dim3(DM/64, MTOT/64, 1), blk>>>(
        x, W_q, q, b_q, MTOT, DM, DM, DM, DM, DM,
        1, 0, 0, 0, 0, 0, 0, 1.0f);

    // 5) scores[bh] = (q_bh @ k_bh^T) / sqrt(Dh)   batched over 64 (b,h)
    gemm_kernel<true><<<dim3(SQ/64, SQ/64, BB*NH), blk>>>(
        q, key, sc, nullptr, SQ, SQ, DH, DM, DM, SQ,
        NH,
        (long long)SQ * DM, (long long)DH,     // A: per-b, per-h
        (long long)SQ * DM, (long long)DH,     // B: per-b, per-h
        (long long)NH * SQ * SQ, (long long)SQ * SQ,  // C: per-b, per-h
        inv_sqrt_dh);

    // 6) softmax over rows of scores
    softmax_kernel<<<BB * NH * SQ, 256>>>(sc);

    // 7) ctx[bh] = P_bh @ v_bh                [2048, 128] per (b,h)
    gemm_kernel<false><<<dim3(DH/64, SQ/64, BB*NH), blk>>>(
        sc, val, ctx, nullptr, SQ, DH, SQ, SQ, DM, DM,
        NH,
        (long long)NH * SQ * SQ, (long long)SQ * SQ,  // A
        (long long)SQ * DM, (long long)DH,            // B
        (long long)SQ * DM, (long long)DH,            // C
        1.0f);

    // 8) out = ctx @ W_o + b_o                [8192, 2048]
    gemm_kernel<false><<<dim3(DM/64, MTOT/64, 1), blk>>>(
        ctx, W_o, out, b_o, MTOT, DM, DM, DM, DM, DM,
        1, 0, 0, 0, 0, 0, 0, 1.0f);
}

// round 4
// speedup vs baseline: 1.4868x; 1.4868x over previous
#include <cuda_runtime.h>
#include <math.h>
#include <stdint.h>

#define SQ   2048
#define DM   2048
#define DH   128
#define NH   16
#define DL   512
#define BB   4
#define MTOT (BB*SQ)

// ---------------- scratch ------------------------------------------------------
__device__ float g_lat[MTOT * DL];
__device__ float g_key[MTOT * DM];
__device__ float g_val[MTOT * DM];
__device__ float g_q[MTOT * DM];
__device__ float g_ctx[MTOT * DM];
__device__ float g_vt[(size_t)BB * NH * DH * SQ];
__device__ float g_wt[DM * DM];
__device__ float g_scores[(size_t)BB * NH * SQ * SQ];

// ---------------- helpers ------------------------------------------------------
__device__ __forceinline__ uint32_t smem_u32(const void* p) {
    uint32_t a;
    asm("{ .reg .u64 t; cvta.to.shared.u64 t, %1; cvt.u32.u64 %0, t; }" : "=r"(a) : "l"(p));
    return a;
}
__device__ __forceinline__ void cp_async16(uint32_t dst, const void* src) {
    asm volatile("cp.async.cg.shared.global [%0], [%1], 16;" :: "r"(dst), "l"(src) : "memory");
}
#define CP_COMMIT() asm volatile("cp.async.commit_group;" ::: "memory")
#define CP_WAIT1()  asm volatile("cp.async.wait_group 1;" ::: "memory")

__device__ __forceinline__ uint32_t to_tf32(float f) {
    uint32_t r;
    asm("cvt.rna.tf32.f32 %0, %1;" : "=r"(r) : "f"(f));
    return r;
}
// split fp32 into tf32 hi + tf32 lo  (a ≈ hi + lo, |lo| ≤ 2^-11 |a|)
__device__ __forceinline__ void split_tf32(float a, uint32_t& hi, uint32_t& lo) {
    hi = to_tf32(a);
    lo = to_tf32(a - __uint_as_float(hi));
}

__device__ __forceinline__ void mma_tf32(float* c, const uint32_t* a, const uint32_t* b) {
    asm volatile(
        "mma.sync.aligned.m16n8k8.row.col.f32.tf32.tf32.f32 "
        "{%0,%1,%2,%3}, {%4,%5,%6,%7}, {%8,%9}, {%0,%1,%2,%3};"
        : "+f"(c[0]), "+f"(c[1]), "+f"(c[2]), "+f"(c[3])
        : "r"(a[0]), "r"(a[1]), "r"(a[2]), "r"(a[3]), "r"(b[0]), "r"(b[1]));
}

// ---------------- 3xTF32 mma.sync GEMM: D[M,N] = scale*(A @ B^T) + bias --------
// A [M,K] row-major (K-major), B [N,K] row-major (K-major).
// M%128==0, N%128==0, K%16==0. Batched via blockIdx.z.
#define SROW 20
#define STAGE_F (2 * 128 * SROW)
#define STAGE_B (STAGE_F * 4)
#define SMEM_GEMM (3 * STAGE_B)

__global__ __launch_bounds__(256, 2)
void mma_gemm(const float* __restrict__ A, const float* __restrict__ B,
              float* __restrict__ C, const float* __restrict__ bias,
              int K, int lda, int ldb, int ldc, int nInner,
              long long aOut, long long aIn,
              long long bOut, long long bIn,
              long long cOut, long long cIn, float scale)
{
    extern __shared__ float sm[];
    const uint32_t smb = smem_u32(sm);

    const int tid  = threadIdx.x;
    const int wid  = tid >> 5;
    const int lane = tid & 31;
    const int qr   = lane >> 2;    // 0..7
    const int qc   = lane & 3;     // 0..3
    const int warpM = (wid & 1) * 64;
    const int warpN = (wid >> 1) * 32;

    const int z = blockIdx.z;
    A += (z / nInner) * aOut + (z % nInner) * aIn;
    B += (z / nInner) * bOut + (z % nInner) * bIn;
    C += (z / nInner) * cOut + (z % nInner) * cIn;
    const int m0 = blockIdx.y * 128;
    const int n0 = blockIdx.x * 128;

    const float* Ab = A + (long long)m0 * lda;
    const float* Bb = B + (long long)n0 * ldb;

    const int r0 = tid >> 2;
    const int ks = tid & 3;

    float acc[4][4][4];
#pragma unroll
    for (int mi = 0; mi < 4; mi++)
#pragma unroll
        for (int ni = 0; ni < 4; ni++)
#pragma unroll
            for (int t = 0; t < 4; t++) acc[mi][ni][t] = 0.0f;

    const int nk = K >> 4;

    auto load_tile = [&](int t, int s) {
        const int k0 = t << 4;
        const uint32_t stA = smb + s * STAGE_B;
        const uint32_t stB = stA + 128 * SROW * 4;
#pragma unroll
        for (int j = 0; j < 2; j++) {
            int r = r0 + j * 64;
            uint32_t off = (uint32_t)(r * SROW + ks * 4) * 4;
            cp_async16(stA + off, Ab + (long long)r * lda + k0 + ks * 4);
            cp_async16(stB + off, Bb + (long long)r * ldb + k0 + ks * 4);
        }
    };

    load_tile(0, 0);
    CP_COMMIT();
    if (nk > 1) load_tile(1, 1);
    CP_COMMIT();

    for (int i = 0; i < nk; i++) {
        CP_WAIT1();
        __syncthreads();
        if (i + 2 < nk) load_tile(i + 2, (i + 2) % 3);
        CP_COMMIT();

        const float* sA = sm + (i % 3) * STAGE_F;
        const float* sB = sA + 128 * SROW;
#pragma unroll
        for (int kk = 0; kk < 16; kk += 8) {
            uint32_t ah[4][4], al[4][4], bh[4][2], bl[4][2];
#pragma unroll
            for (int mi = 0; mi < 4; mi++) {
                int row = warpM + mi * 16 + qr;
                split_tf32(sA[row * SROW + kk + qc],           ah[mi][0], al[mi][0]);
                split_tf32(sA[(row + 8) * SROW + kk + qc],     ah[mi][1], al[mi][1]);
                split_tf32(sA[row * SROW + kk + qc + 4],       ah[mi][2], al[mi][2]);
                split_tf32(sA[(row + 8) * SROW + kk + qc + 4], ah[mi][3], al[mi][3]);
            }
#pragma unroll
            for (int ni = 0; ni < 4; ni++) {
                int col = warpN + ni * 8 + qr;
                split_tf32(sB[col * SROW + kk + qc],     bh[ni][0], bl[ni][0]);
                split_tf32(sB[col * SROW + kk + qc + 4], bh[ni][1], bl[ni][1]);
            }
#pragma unroll
            for (int mi = 0; mi < 4; mi++)
#pragma unroll
                for (int ni = 0; ni < 4; ni++) {
                    mma_tf32(acc[mi][ni], al[mi], bh[ni]);   // lo*hi
                    mma_tf32(acc[mi][ni], ah[mi], bl[ni]);   // hi*lo
                    mma_tf32(acc[mi][ni], ah[mi], bh[ni]);   // hi*hi last (largest)
                }
        }
    }

    // ---- epilogue ----
#pragma unroll
    for (int mi = 0; mi < 4; mi++) {
#pragma unroll
        for (int ni = 0; ni < 4; ni++) {
            int row = m0 + warpM + mi * 16 + qr;
            int col = n0 + warpN + ni * 8 + qc * 2;
            float2 bv = make_float2(0.f, 0.f);
            if (bias) bv = *(const float2*)(bias + col);
            float2 v0, v1;
            v0.x = acc[mi][ni][0] * scale + bv.x;
            v0.y = acc[mi][ni][1] * scale + bv.y;
            v1.x = acc[mi][ni][2] * scale + bv.x;
            v1.y = acc[mi][ni][3] * scale + bv.y;
            *(float2*)(C + (long long)row * ldc + col) = v0;
            *(float2*)(C + (long long)(row + 8) * ldc + col) = v1;
        }
    }
}

// ---------------- batched tiled transpose --------------------------------------
__global__ void transpose_kernel(const float* __restrict__ in, float* __restrict__ out,
                                 long long ldi, long long ldo, int nInner,
                                 long long iOut, long long iIn,
                                 long long oOut, long long oIn)
{
    __shared__ float t[32][33];
    const int z = blockIdx.z;
    in  += (z / nInner) * iOut + (z % nInner) * iIn;
    out += (z / nInner) * oOut + (z % nInner) * oIn;
    const int c0 = blockIdx.x * 32, r0 = blockIdx.y * 32;
#pragma unroll
    for (int i = threadIdx.y; i < 32; i += 8)
        t[i][threadIdx.x] = in[(long long)(r0 + i) * ldi + c0 + threadIdx.x];
    __syncthreads();
#pragma unroll
    for (int i = threadIdx.y; i < 32; i += 8)
        out[(long long)(c0 + i) * ldo + r0 + threadIdx.x] = t[threadIdx.x][i];
}

// ---------------- row softmax (row length 2048) --------------------------------
__launch_bounds__(256)
__global__ void softmax_kernel(float* __restrict__ P)
{
    const long long row = blockIdx.x;
    float* p = P + row * SQ;
    const int tid = threadIdx.x;

    float4 v1 = ((const float4*)p)[tid];
    float4 v2 = ((const float4*)p)[256 + tid];
    float m = fmaxf(fmaxf(fmaxf(v1.x, v1.y), fmaxf(v1.z, v1.w)),
                    fmaxf(fmaxf(v2.x, v2.y), fmaxf(v2.z, v2.w)));
    __shared__ float red[256];
    red[tid] = m; __syncthreads();
    for (int s = 128; s > 0; s >>= 1) { if (tid < s) red[tid] = fmaxf(red[tid], red[tid + s]); __syncthreads(); }
    const float rowmax = red[0]; __syncthreads();

    v1.x = __expf(v1.x - rowmax); v1.y = __expf(v1.y - rowmax);
    v1.z = __expf(v1.z - rowmax); v1.w = __expf(v1.w - rowmax);
    v2.x = __expf(v2.x - rowmax); v2.y = __expf(v2.y - rowmax);
    v2.z = __expf(v2.z - rowmax); v2.w = __expf(v2.w - rowmax);
    float s8 = (v1.x + v1.y) + (v1.z + v1.w) + (v2.x + v2.y) + (v2.z + v2.w);
    red[tid] = s8; __syncthreads();
    for (int s = 128; s > 0; s >>= 1) { if (tid < s) red[tid] += red[tid + s]; __syncthreads(); }
    const float inv = 1.0f / red[0];

    v1.x *= inv; v1.y *= inv; v1.z *= inv; v1.w *= inv;
    v2.x *= inv; v2.y *= inv; v2.z *= inv; v2.w *= inv;
    ((float4*)p)[tid] = v1;
    ((float4*)p)[256 + tid] = v2;
}

// ---------------- launch -------------------------------------------------------
extern "C" void kernel_launch(void* const* d_in, const int* in_sizes, int n_in,
                              void* d_out, int out_size)
{
    const float* x      = (const float*)d_in[0];
    const float* W_down = (const float*)d_in[1];
    const float* b_down = (const float*)d_in[2];
    const float* W_uk   = (const float*)d_in[3];
    const float* b_uk   = (const float*)d_in[4];
    const float* W_uv   = (const float*)d_in[5];
    const float* b_uv   = (const float*)d_in[6];
    const float* W_q    = (const float*)d_in[7];
    const float* b_q    = (const float*)d_in[8];
    const float* W_o    = (const float*)d_in[9];
    const float* b_o    = (const float*)d_in[10];
    float* out = (float*)d_out;

    void *p0, *p1, *p2, *p3, *p4, *p5, *p6, *p7;
    cudaGetSymbolAddress(&p0, g_lat);    float* lat = (float*)p0;
    cudaGetSymbolAddress(&p1, g_key);    float* key = (float*)p1;
    cudaGetSymbolAddress(&p2, g_val);    float* val = (float*)p2;
    cudaGetSymbolAddress(&p3, g_q);      float* q   = (float*)p3;
    cudaGetSymbolAddress(&p4, g_ctx);    float* ctx = (float*)p4;
    cudaGetSymbolAddress(&p5, g_vt);     float* vt  = (float*)p5;
    cudaGetSymbolAddress(&p6, g_wt);     float* wt  = (float*)p6;
    cudaGetSymbolAddress(&p7, g_scores); float* sc  = (float*)p7;

    static bool attr_set = false;
    if (!attr_set) {
        cudaFuncSetAttribute(mma_gemm, cudaFuncAttributeMaxDynamicSharedMemorySize, SMEM_GEMM);
        attr_set = true;
    }

    const float inv_sqrt_dh = 0.08838834764831845f;
    dim3 blk(256);

    // 1) latents = x @ W_down + b_down
    transpose_kernel<<<dim3(DL/32, DM/32, 1), dim3(32,8)>>>(W_down, wt, DL, DM, 1, 0,0,0,0);
    mma_gemm<<<dim3(DL/128, MTOT/128, 1), blk, SMEM_GEMM>>>(
        x, wt, lat, b_down, DM, DM, DM, DL, 1, 0,0,0,0,0,0, 1.0f);

    // 2) keys = latents @ W_uk + b_uk
    transpose_kernel<<<dim3(DM/32, DL/32, 1), dim3(32,8)>>>(W_uk, wt, DM, DL, 1, 0,0,0,0);
    mma_gemm<<<dim3(DM/128, MTOT/128, 1), blk, SMEM_GEMM>>>(
        lat, wt, key, b_uk, DL, DL, DL, DM, 1, 0,0,0,0,0,0, 1.0f);

    // 3) values = latents @ W_uv + b_uv
    transpose_kernel<<<dim3(DM/32, DL/32, 1), dim3(32,8)>>>(W_uv, wt, DM, DL, 1, 0,0,0,0);
    mma_gemm<<<dim3(DM/128, MTOT/128, 1), blk, SMEM_GEMM>>>(
        lat, wt, val, b_uv, DL, DL, DL, DM, 1, 0,0,0,0,0,0, 1.0f);

    // 4) q = x @ W_q + b_q
    transpose_kernel<<<dim3(DM/32, DM/32, 1), dim3(32,8)>>>(W_q, wt, DM, DM, 1, 0,0,0,0);
    mma_gemm<<<dim3(DM/128, MTOT/128, 1), blk, SMEM_GEMM>>>(
        x, wt, q, b_q, DM, DM, DM, DM, 1, 0,0,0,0,0,0, 1.0f);

    // 5) scores[bh] = (q_bh @ k_bh^T)/sqrt(Dh)
    mma_gemm<<<dim3(SQ/128, SQ/128, BB*NH), blk, SMEM_GEMM>>>(
        q, key, sc, nullptr, DH, DM, DM, SQ, NH,
        (long long)SQ * DM, (long long)DH,
        (long long)SQ * DM, (long long)DH,
        (long long)NH * SQ * SQ, (long long)SQ * SQ, inv_sqrt_dh);

    // 6) softmax
    softmax_kernel<<<BB * NH * SQ, 256>>>(sc);

    // 7) vt[bh] = v_bh^T ; ctx[bh] = P_bh @ vt^T
    transpose_kernel<<<dim3(DH/32, SQ/32, BB*NH), dim3(32,8)>>>(
        val, vt, DM, SQ, NH,
        (long long)SQ * DM, (long long)DH,
        (long long)NH * DH * SQ, (long long)DH * SQ);
    mma_gemm<<<dim3(DH/128, SQ/128, BB*NH), blk, SMEM_GEMM>>>(
        sc, vt, ctx, nullptr, SQ, SQ, SQ, DM, NH,
        (long long)NH * SQ * SQ, (long long)SQ * SQ,
        (long long)NH * DH * SQ, (long long)DH * SQ,
        (long long)SQ * DM, (long long)DH, 1.0f);

    // 8) out = ctx @ W_o + b_o
    transpose_kernel<<<dim3(DM/32, DM/32, 1), dim3(32,8)>>>(W_o, wt, DM, DM, 1, 0,0,0,0);
    mma_gemm<<<dim3(DM/128, MTOT/128, 1), blk, SMEM_GEMM>>>(
        ctx, wt, out, b_o, DM, DM, DM, DM, 1, 0,0,0,0,0,0, 1.0f);
}

// round 5
// speedup vs baseline: 2.2935x; 1.5426x over previous
#include <cuda_runtime.h>
#include <cuda_fp16.h>
#include <math.h>
#include <stdint.h>

#define SQ   2048
#define DM   2048
#define DH   128
#define NH   16
#define DL   512
#define BB   4
#define MTOT (BB*SQ)

// ---------------- scratch ------------------------------------------------------
__device__ float g_lat[MTOT * DL];
__device__ float g_key[MTOT * DM];
__device__ float g_val[MTOT * DM];
__device__ float g_q[MTOT * DM];
__device__ float g_ctx[MTOT * DM];
__device__ float g_vt[(size_t)BB * NH * DH * SQ];
__device__ float g_wt[DM * DM];
__device__ float g_scores[(size_t)BB * NH * SQ * SQ];

// ---------------- helpers ------------------------------------------------------
__device__ __forceinline__ uint32_t smem_u32(const void* p) {
    uint32_t a;
    asm("{ .reg .u64 t; cvta.to.shared.u64 t, %1; cvt.u32.u64 %0, t; }" : "=r"(a) : "l"(p));
    return a;
}
__device__ __forceinline__ void cp_async16(uint32_t dst, const void* src) {
    asm volatile("cp.async.cg.shared.global [%0], [%1], 16;" :: "r"(dst), "l"(src) : "memory");
}
#define CP_COMMIT() asm volatile("cp.async.commit_group;" ::: "memory")
#define CP_WAIT1()  asm volatile("cp.async.wait_group 1;" ::: "memory")

// split float2 into fp16x2 hi + fp16x2 lo  (a ≈ hi + lo, residual ~2^-22)
__device__ __forceinline__ void split_h2(float2 f, uint32_t& hi, uint32_t& lo) {
    __half2 h = __float22half2_rn(f);
    float2 back = __half22float2(h);
    __half2 l = __float22half2_rn(make_float2(f.x - back.x, f.y - back.y));
    hi = *(uint32_t*)&h;
    lo = *(uint32_t*)&l;
}

__device__ __forceinline__ void mma_f16(float* c, const uint32_t* a, const uint32_t* b) {
    asm volatile(
        "mma.sync.aligned.m16n8k16.row.col.f32.f16.f16.f32 "
        "{%0,%1,%2,%3}, {%4,%5,%6,%7}, {%8,%9}, {%0,%1,%2,%3};"
        : "+f"(c[0]), "+f"(c[1]), "+f"(c[2]), "+f"(c[3])
        : "r"(a[0]), "r"(a[1]), "r"(a[2]), "r"(a[3]), "r"(b[0]), "r"(b[1]));
}

// ---------------- 3xFP16 mma.sync GEMM: D[M,N] = scale*(A @ B^T) + bias --------
// A [M,K] row-major (K-major), B [N,K] row-major (K-major).
// M%128==0, N%128==0, K%16==0. Batched via blockIdx.z.
#define SROW 20
#define STAGE_F (2 * 128 * SROW)
#define STAGE_B (STAGE_F * 4)
#define SMEM_GEMM (3 * STAGE_B)

__global__ __launch_bounds__(256, 2)
void mma_gemm(const float* __restrict__ A, const float* __restrict__ B,
              float* __restrict__ C, const float* __restrict__ bias,
              int K, int lda, int ldb, int ldc, int nInner,
              long long aOut, long long aIn,
              long long bOut, long long bIn,
              long long cOut, long long cIn, float scale)
{
    extern __shared__ float sm[];
    const uint32_t smb = smem_u32(sm);

    const int tid  = threadIdx.x;
    const int wid  = tid >> 5;
    const int lane = tid & 31;
    const int qr   = lane >> 2;    // 0..7
    const int qc   = lane & 3;     // 0..3
    const int warpM = (wid & 1) * 64;
    const int warpN = (wid >> 1) * 32;

    const int z = blockIdx.z;
    A += (z / nInner) * aOut + (z % nInner) * aIn;
    B += (z / nInner) * bOut + (z % nInner) * bIn;
    C += (z / nInner) * cOut + (z % nInner) * cIn;
    const int m0 = blockIdx.y * 128;
    const int n0 = blockIdx.x * 128;

    const float* Ab = A + (long long)m0 * lda;
    const float* Bb = B + (long long)n0 * ldb;

    const int r0 = tid >> 2;
    const int ks = tid & 3;

    float acc[4][4][4];
#pragma unroll
    for (int mi = 0; mi < 4; mi++)
#pragma unroll
        for (int ni = 0; ni < 4; ni++)
#pragma unroll
            for (int t = 0; t < 4; t++) acc[mi][ni][t] = 0.0f;

    const int nk = K >> 4;

    auto load_tile = [&](int t, int s) {
        const int k0 = t << 4;
        const uint32_t stA = smb + s * STAGE_B;
        const uint32_t stB = stA + 128 * SROW * 4;
#pragma unroll
        for (int j = 0; j < 2; j++) {
            int r = r0 + j * 64;
            uint32_t off = (uint32_t)(r * SROW + ks * 4) * 4;
            cp_async16(stA + off, Ab + (long long)r * lda + k0 + ks * 4);
            cp_async16(stB + off, Bb + (long long)r * ldb + k0 + ks * 4);
        }
    };

    load_tile(0, 0);
    CP_COMMIT();
    if (nk > 1) load_tile(1, 1);
    CP_COMMIT();

    for (int i = 0; i < nk; i++) {
        CP_WAIT1();
        __syncthreads();
        if (i + 2 < nk) load_tile(i + 2, (i + 2) % 3);
        CP_COMMIT();

        const float* sA = sm + (i % 3) * STAGE_F;
        const float* sB = sA + 128 * SROW;

        uint32_t ah[4][4], al[4][4], bh[4][2], bl[4][2];
#pragma unroll
        for (int mi = 0; mi < 4; mi++) {
            int row = warpM + mi * 16 + qr;
            split_h2(*(const float2*)&sA[row * SROW + qc * 2],           ah[mi][0], al[mi][0]);
            split_h2(*(const float2*)&sA[(row + 8) * SROW + qc * 2],     ah[mi][1], al[mi][1]);
            split_h2(*(const float2*)&sA[row * SROW + qc * 2 + 8],       ah[mi][2], al[mi][2]);
            split_h2(*(const float2*)&sA[(row + 8) * SROW + qc * 2 + 8], ah[mi][3], al[mi][3]);
        }
#pragma unroll
        for (int ni = 0; ni < 4; ni++) {
            int col = warpN + ni * 8 + qr;
            split_h2(*(const float2*)&sB[col * SROW + qc * 2],     bh[ni][0], bl[ni][0]);
            split_h2(*(const float2*)&sB[col * SROW + qc * 2 + 8], bh[ni][1], bl[ni][1]);
        }
#pragma unroll
        for (int mi = 0; mi < 4; mi++)
#pragma unroll
            for (int ni = 0; ni < 4; ni++) {
                mma_f16(acc[mi][ni], al[mi], bh[ni]);   // lo*hi
                mma_f16(acc[mi][ni], ah[mi], bl[ni]);   // hi*lo
                mma_f16(acc[mi][ni], ah[mi], bh[ni]);   // hi*hi last (largest)
            }
    }

    // ---- epilogue ----
#pragma unroll
    for (int mi = 0; mi < 4; mi++) {
#pragma unroll
        for (int ni = 0; ni < 4; ni++) {
            int row = m0 + warpM + mi * 16 + qr;
            int col = n0 + warpN + ni * 8 + qc * 2;
            float2 bv = make_float2(0.f, 0.f);
            if (bias) bv = *(const float2*)(bias + col);
            float2 v0, v1;
            v0.x = acc[mi][ni][0] * scale + bv.x;
            v0.y = acc[mi][ni][1] * scale + bv.y;
            v1.x = acc[mi][ni][2] * scale + bv.x;
            v1.y = acc[mi][ni][3] * scale + bv.y;
            *(float2*)(C + (long long)row * ldc + col) = v0;
            *(float2*)(C + (long long)(row + 8) * ldc + col) = v1;
        }
    }
}

// ---------------- batched tiled transpose --------------------------------------
__global__ void transpose_kernel(const float* __restrict__ in, float* __restrict__ out,
                                 long long ldi, long long ldo, int nInner,
                                 long long iOut, long long iIn,
                                 long long oOut, long long oIn)
{
    __shared__ float t[32][33];
    const int z = blockIdx.z;
    in  += (z / nInner) * iOut + (z % nInner) * iIn;
    out += (z / nInner) * oOut + (z % nInner) * oIn;
    const int c0 = blockIdx.x * 32, r0 = blockIdx.y * 32;
#pragma unroll
    for (int i = threadIdx.y; i < 32; i += 8)
        t[i][threadIdx.x] = in[(long long)(r0 + i) * ldi + c0 + threadIdx.x];
    __syncthreads();
#pragma unroll
    for (int i = threadIdx.y; i < 32; i += 8)
        out[(long long)(c0 + i) * ldo + r0 + threadIdx.x] = t[threadIdx.x][i];
}

// ---------------- row softmax (row length 2048) --------------------------------
// Writes P * 1024 so the fp16 lo-split of small probabilities stays normal;
// the PV GEMM compensates with scale = 1/1024.
__launch_bounds__(256)
__global__ void softmax_kernel(float* __restrict__ P)
{
    const long long row = blockIdx.x;
    float* p = P + row * SQ;
    const int tid = threadIdx.x;

    float4 v1 = ((const float4*)p)[tid];
    float4 v2 = ((const float4*)p)[256 + tid];
    float m = fmaxf(fmaxf(fmaxf(v1.x, v1.y), fmaxf(v1.z, v1.w)),
                    fmaxf(fmaxf(v2.x, v2.y), fmaxf(v2.z, v2.w)));
    __shared__ float red[256];
    red[tid] = m; __syncthreads();
    for (int s = 128; s > 0; s >>= 1) { if (tid < s) red[tid] = fmaxf(red[tid], red[tid + s]); __syncthreads(); }
    const float rowmax = red[0]; __syncthreads();

    v1.x = __expf(v1.x - rowmax); v1.y = __expf(v1.y - rowmax);
    v1.z = __expf(v1.z - rowmax); v1.w = __expf(v1.w - rowmax);
    v2.x = __expf(v2.x - rowmax); v2.y = __expf(v2.y - rowmax);
    v2.z = __expf(v2.z - rowmax); v2.w = __expf(v2.w - rowmax);
    float s8 = (v1.x + v1.y) + (v1.z + v1.w) + (v2.x + v2.y) + (v2.z + v2.w);
    red[tid] = s8; __syncthreads();
    for (int s = 128; s > 0; s >>= 1) { if (tid < s) red[tid] += red[tid + s]; __syncthreads(); }
    const float inv = 1024.0f / red[0];

    v1.x *= inv; v1.y *= inv; v1.z *= inv; v1.w *= inv;
    v2.x *= inv; v2.y *= inv; v2.z *= inv; v2.w *= inv;
    ((float4*)p)[tid] = v1;
    ((float4*)p)[256 + tid] = v2;
}

// ---------------- launch -------------------------------------------------------
extern "C" void kernel_launch(void* const* d_in, const int* in_sizes, int n_in,
                              void* d_out, int out_size)
{
    const float* x      = (const float*)d_in[0];
    const float* W_down = (const float*)d_in[1];
    const float* b_down = (const float*)d_in[2];
    const float* W_uk   = (const float*)d_in[3];
    const float* b_uk   = (const float*)d_in[4];
    const float* W_uv   = (const float*)d_in[5];
    const float* b_uv   = (const float*)d_in[6];
    const float* W_q    = (const float*)d_in[7];
    const float* b_q    = (const float*)d_in[8];
    const float* W_o    = (const float*)d_in[9];
    const float* b_o    = (const float*)d_in[10];
    float* out = (float*)d_out;

    void *p0, *p1, *p2, *p3, *p4, *p5, *p6, *p7;
    cudaGetSymbolAddress(&p0, g_lat);    float* lat = (float*)p0;
    cudaGetSymbolAddress(&p1, g_key);    float* key = (float*)p1;
    cudaGetSymbolAddress(&p2, g_val);    float* val = (float*)p2;
    cudaGetSymbolAddress(&p3, g_q);      float* q   = (float*)p3;
    cudaGetSymbolAddress(&p4, g_ctx);    float* ctx = (float*)p4;
    cudaGetSymbolAddress(&p5, g_vt);     float* vt  = (float*)p5;
    cudaGetSymbolAddress(&p6, g_wt);     float* wt  = (float*)p6;
    cudaGetSymbolAddress(&p7, g_scores); float* sc  = (float*)p7;

    static bool attr_set = false;
    if (!attr_set) {
        cudaFuncSetAttribute(mma_gemm, cudaFuncAttributeMaxDynamicSharedMemorySize, SMEM_GEMM);
        attr_set = true;
    }

    const float inv_sqrt_dh = 0.08838834764831845f;
    dim3 blk(256);

    // 1) latents = x @ W_down + b_down
    transpose_kernel<<<dim3(DL/32, DM/32, 1), dim3(32,8)>>>(W_down, wt, DL, DM, 1, 0,0,0,0);
    mma_gemm<<<dim3(DL/128, MTOT/128, 1), blk, SMEM_GEMM>>>(
        x, wt, lat, b_down, DM, DM, DM, DL, 1, 0,0,0,0,0,0, 1.0f);

    // 2) keys = latents @ W_uk + b_uk
    transpose_kernel<<<dim3(DM/32, DL/32, 1), dim3(32,8)>>>(W_uk, wt, DM, DL, 1, 0,0,0,0);
    mma_gemm<<<dim3(DM/128, MTOT/128, 1), blk, SMEM_GEMM>>>(
        lat, wt, key, b_uk, DL, DL, DL, DM, 1, 0,0,0,0,0,0, 1.0f);

    // 3) values = latents @ W_uv + b_uv
    transpose_kernel<<<dim3(DM/32, DL/32, 1), dim3(32,8)>>>(W_uv, wt, DM, DL, 1, 0,0,0,0);
    mma_gemm<<<dim3(DM/128, MTOT/128, 1), blk, SMEM_GEMM>>>(
        lat, wt, val, b_uv, DL, DL, DL, DM, 1, 0,0,0,0,0,0, 1.0f);

    // 4) q = x @ W_q + b_q
    transpose_kernel<<<dim3(DM/32, DM/32, 1), dim3(32,8)>>>(W_q, wt, DM, DM, 1, 0,0,0,0);
    mma_gemm<<<dim3(DM/128, MTOT/128, 1), blk, SMEM_GEMM>>>(
        x, wt, q, b_q, DM, DM, DM, DM, 1, 0,0,0,0,0,0, 1.0f);

    // 5) scores[bh] = (q_bh @ k_bh^T)/sqrt(Dh)
    mma_gemm<<<dim3(SQ/128, SQ/128, BB*NH), blk, SMEM_GEMM>>>(
        q, key, sc, nullptr, DH, DM, DM, SQ, NH,
        (long long)SQ * DM, (long long)DH,
        (long long)SQ * DM, (long long)DH,
        (long long)NH * SQ * SQ, (long long)SQ * SQ, inv_sqrt_dh);

    // 6) softmax (outputs P * 1024)
    softmax_kernel<<<BB * NH * SQ, 256>>>(sc);

    // 7) vt[bh] = v_bh^T ; ctx[bh] = (P*1024 @ vt^T) / 1024
    transpose_kernel<<<dim3(DH/32, SQ/32, BB*NH), dim3(32,8)>>>(
        val, vt, DM, SQ, NH,
        (long long)SQ * DM, (long long)DH,
        (long long)NH * DH * SQ, (long long)DH * SQ);
    mma_gemm<<<dim3(DH/128, SQ/128, BB*NH), blk, SMEM_GEMM>>>(
        sc, vt, ctx, nullptr, SQ, SQ, SQ, DM, NH,
        (long long)NH * SQ * SQ, (long long)SQ * SQ,
        (long long)NH * DH * SQ, (long long)DH * SQ,
        (long long)SQ * DM, (long long)DH, 0.0009765625f);

    // 8) out = ctx @ W_o + b_o
    transpose_kernel<<<dim3(DM/32, DM/32, 1), dim3(32,8)>>>(W_o, wt, DM, DM, 1, 0,0,0,0);
    mma_gemm<<<dim3(DM/128, MTOT/128, 1), blk, SMEM_GEMM>>>(
        ctx, wt, out, b_o, DM, DM, DM, DM, 1, 0,0,0,0,0,0, 1.0f);
}

// round 6
// speedup vs baseline: 2.5433x; 1.1089x over previous
#include <cuda_runtime.h>
#include <cuda_fp16.h>
#include <math.h>
#include <stdint.h>

#define SQ   2048
#define DM   2048
#define DH   128
#define NH   16
#define DL   512
#define BB   4
#define MTOT (BB*SQ)

// ---------------- scratch ------------------------------------------------------
__device__ float  g_lat[MTOT * DL];
__device__ float  g_key[MTOT * DM];
__device__ float  g_val[MTOT * DM];
__device__ float  g_q[MTOT * DM];
__device__ float  g_ctx[MTOT * DM];
__device__ float  g_wt[DM * DM];
__device__ __half g_khi[(size_t)MTOT * DM];
__device__ __half g_klo[(size_t)MTOT * DM];
__device__ __half g_vthi[(size_t)BB * NH * DH * SQ];
__device__ __half g_vtlo[(size_t)BB * NH * DH * SQ];

// ---------------- helpers ------------------------------------------------------
__device__ __forceinline__ uint32_t smem_u32(const void* p) {
    uint32_t a;
    asm("{ .reg .u64 t; cvta.to.shared.u64 t, %1; cvt.u32.u64 %0, t; }" : "=r"(a) : "l"(p));
    return a;
}
__device__ __forceinline__ void cp_async16(uint32_t dst, const void* src) {
    asm volatile("cp.async.cg.shared.global [%0], [%1], 16;" :: "r"(dst), "l"(src) : "memory");
}
#define CP_COMMIT() asm volatile("cp.async.commit_group;" ::: "memory")
#define CP_WAIT1()  asm volatile("cp.async.wait_group 1;" ::: "memory")
#define CP_WAIT0()  asm volatile("cp.async.wait_group 0;" ::: "memory")

__device__ __forceinline__ void split_h2(float2 f, uint32_t& hi, uint32_t& lo) {
    __half2 h = __float22half2_rn(f);
    float2 back = __half22float2(h);
    __half2 l = __float22half2_rn(make_float2(f.x - back.x, f.y - back.y));
    hi = *(uint32_t*)&h;
    lo = *(uint32_t*)&l;
}

__device__ __forceinline__ void mma_f16(float* c, const uint32_t* a, const uint32_t* b) {
    asm volatile(
        "mma.sync.aligned.m16n8k16.row.col.f32.f16.f16.f32 "
        "{%0,%1,%2,%3}, {%4,%5,%6,%7}, {%8,%9}, {%0,%1,%2,%3};"
        : "+f"(c[0]), "+f"(c[1]), "+f"(c[2]), "+f"(c[3])
        : "r"(a[0]), "r"(a[1]), "r"(a[2]), "r"(a[3]), "r"(b[0]), "r"(b[1]));
}

// pair permutation within 16-element groups so that a B-fragment's
// {k=2q, 2q+1, 2q+8, 2q+9} become 4 contiguous halves (one 8B load)
__device__ __forceinline__ int inv_pair(int p) { return ((p & 3) << 1) | (p >> 2); }

// ---------------- 3xFP16 mma.sync GEMM (projections) ---------------------------
#define SROW 20
#define STAGE_F (2 * 128 * SROW)
#define STAGE_B (STAGE_F * 4)
#define SMEM_GEMM (3 * STAGE_B)

__global__ __launch_bounds__(256, 2)
void mma_gemm(const float* __restrict__ A, const float* __restrict__ B,
              float* __restrict__ C, const float* __restrict__ bias,
              int K, int lda, int ldb, int ldc, float scale)
{
    extern __shared__ float sm[];
    const uint32_t smb = smem_u32(sm);

    const int tid  = threadIdx.x;
    const int wid  = tid >> 5;
    const int lane = tid & 31;
    const int qr   = lane >> 2;
    const int qc   = lane & 3;
    const int warpM = (wid & 1) * 64;
    const int warpN = (wid >> 1) * 32;

    const int m0 = blockIdx.y * 128;
    const int n0 = blockIdx.x * 128;

    const float* Ab = A + (long long)m0 * lda;
    const float* Bb = B + (long long)n0 * ldb;

    const int r0 = tid >> 2;
    const int ks = tid & 3;

    float acc[4][4][4];
#pragma unroll
    for (int mi = 0; mi < 4; mi++)
#pragma unroll
        for (int ni = 0; ni < 4; ni++)
#pragma unroll
            for (int t = 0; t < 4; t++) acc[mi][ni][t] = 0.0f;

    const int nk = K >> 4;

    auto load_tile = [&](int t, int s) {
        const int k0 = t << 4;
        const uint32_t stA = smb + s * STAGE_B;
        const uint32_t stB = stA + 128 * SROW * 4;
#pragma unroll
        for (int j = 0; j < 2; j++) {
            int r = r0 + j * 64;
            uint32_t off = (uint32_t)(r * SROW + ks * 4) * 4;
            cp_async16(stA + off, Ab + (long long)r * lda + k0 + ks * 4);
            cp_async16(stB + off, Bb + (long long)r * ldb + k0 + ks * 4);
        }
    };

    load_tile(0, 0);
    CP_COMMIT();
    if (nk > 1) load_tile(1, 1);
    CP_COMMIT();

    for (int i = 0; i < nk; i++) {
        CP_WAIT1();
        __syncthreads();
        if (i + 2 < nk) load_tile(i + 2, (i + 2) % 3);
        CP_COMMIT();

        const float* sA = sm + (i % 3) * STAGE_F;
        const float* sB = sA + 128 * SROW;

        uint32_t ah[4][4], al[4][4], bh[4][2], bl[4][2];
#pragma unroll
        for (int mi = 0; mi < 4; mi++) {
            int row = warpM + mi * 16 + qr;
            split_h2(*(const float2*)&sA[row * SROW + qc * 2],           ah[mi][0], al[mi][0]);
            split_h2(*(const float2*)&sA[(row + 8) * SROW + qc * 2],     ah[mi][1], al[mi][1]);
            split_h2(*(const float2*)&sA[row * SROW + qc * 2 + 8],       ah[mi][2], al[mi][2]);
            split_h2(*(const float2*)&sA[(row + 8) * SROW + qc * 2 + 8], ah[mi][3], al[mi][3]);
        }
#pragma unroll
        for (int ni = 0; ni < 4; ni++) {
            int col = warpN + ni * 8 + qr;
            split_h2(*(const float2*)&sB[col * SROW + qc * 2],     bh[ni][0], bl[ni][0]);
            split_h2(*(const float2*)&sB[col * SROW + qc * 2 + 8], bh[ni][1], bl[ni][1]);
        }
#pragma unroll
        for (int mi = 0; mi < 4; mi++)
#pragma unroll
            for (int ni = 0; ni < 4; ni++) {
                mma_f16(acc[mi][ni], al[mi], bh[ni]);
                mma_f16(acc[mi][ni], ah[mi], bl[ni]);
                mma_f16(acc[mi][ni], ah[mi], bh[ni]);
            }
    }

#pragma unroll
    for (int mi = 0; mi < 4; mi++) {
#pragma unroll
        for (int ni = 0; ni < 4; ni++) {
            int row = m0 + warpM + mi * 16 + qr;
            int col = n0 + warpN + ni * 8 + qc * 2;
            float2 bv = make_float2(0.f, 0.f);
            if (bias) bv = *(const float2*)(bias + col);
            float2 v0, v1;
            v0.x = acc[mi][ni][0] * scale + bv.x;
            v0.y = acc[mi][ni][1] * scale + bv.y;
            v1.x = acc[mi][ni][2] * scale + bv.x;
            v1.y = acc[mi][ni][3] * scale + bv.y;
            *(float2*)(C + (long long)row * ldc + col) = v0;
            *(float2*)(C + (long long)(row + 8) * ldc + col) = v1;
        }
    }
}

// ---------------- weight transpose ---------------------------------------------
__global__ void transpose_kernel(const float* __restrict__ in, float* __restrict__ out,
                                 long long ldi, long long ldo)
{
    __shared__ float t[32][33];
    const int c0 = blockIdx.x * 32, r0 = blockIdx.y * 32;
#pragma unroll
    for (int i = threadIdx.y; i < 32; i += 8)
        t[i][threadIdx.x] = in[(long long)(r0 + i) * ldi + c0 + threadIdx.x];
    __syncthreads();
#pragma unroll
    for (int i = threadIdx.y; i < 32; i += 8)
        out[(long long)(c0 + i) * ldo + r0 + threadIdx.x] = t[threadIdx.x][i];
}

// ---------------- split K -> fp16 hi/lo, pair-permuted in d --------------------
__global__ void split_k_kernel(const float* __restrict__ in,
                               __half* __restrict__ hi, __half* __restrict__ lo)
{
    long long i2 = (long long)blockIdx.x * blockDim.x + threadIdx.x;  // float2 index
    if (i2 >= (long long)MTOT * DM / 2) return;
    int d2 = (int)(i2 & (DM / 2 - 1));
    long long row = i2 >> 10;                          // / (DM/2)
    int d2p = (d2 & ~7) | inv_pair(d2 & 7);
    float2 v = ((const float2*)in)[i2];
    uint32_t h, l;
    split_h2(v, h, l);
    ((uint32_t*)hi)[row * (DM / 2) + d2p] = h;
    ((uint32_t*)lo)[row * (DM / 2) + d2p] = l;
}

// ---------------- split+transpose V -> V^T fp16 hi/lo, pair-permuted in s ------
__global__ void split_vt_kernel(const float* __restrict__ in,
                                __half* __restrict__ hi, __half* __restrict__ lo)
{
    __shared__ float t[32][33];
    const int bh = blockIdx.z, b = bh >> 4, h = bh & 15;
    const int s0 = blockIdx.x * 32, d0 = blockIdx.y * 32;
    const float* src = in + (long long)(b * SQ) * DM + h * DH;
#pragma unroll
    for (int i = threadIdx.y; i < 32; i += 8)
        t[i][threadIdx.x] = src[(long long)(s0 + i) * DM + d0 + threadIdx.x];
    __syncthreads();
    const int tx = threadIdx.x;
    const int r = tx & 15;
    const int sperm = (tx & 16) | (inv_pair(r >> 1) * 2 + (r & 1));
#pragma unroll
    for (int i = threadIdx.y; i < 32; i += 8) {
        float v = t[tx][i];
        __half hv = __float2half_rn(v);
        __half lv = __float2half_rn(v - __half2float(hv));
        long long off = ((long long)bh * DH + d0 + i) * SQ + s0 + sperm;
        hi[off] = hv;
        lo[off] = lv;
    }
}

// ---------------- fused flash attention ----------------------------------------
// grid (SQ/128, BB*NH), block 256. Each CTA: 128 q rows of one (b,h).
#define CHUNK 64
#define KROWB 272                      // 64x128 half + 16B pad per row
#define KH_OFF 0
#define KL_OFF (64 * KROWB)            // 17408
#define VH_OFF (2 * 64 * KROWB)        // 34816
#define VROWB 144                      // 128x64 half + 16B pad per row
#define VL_OFF (VH_OFF + 128 * VROWB)  // 53248
#define SMEM_FLASH (VL_OFF + 128 * VROWB)  // 71680

__global__ __launch_bounds__(256)
void flash_kernel(const float* __restrict__ Q,
                  const __half* __restrict__ Khi, const __half* __restrict__ Klo,
                  const __half* __restrict__ Vhi, const __half* __restrict__ Vlo,
                  float* __restrict__ ctx)
{
    extern __shared__ char smc[];
    const uint32_t smb = smem_u32(smc);
    const int tid = threadIdx.x, wid = tid >> 5, lane = tid & 31;
    const int qr = lane >> 2, qc = lane & 3;
    const int bh = blockIdx.y, b = bh >> 4, h = bh & 15;
    const int q0 = blockIdx.x * 128;

    // ---- Q fragments in registers (pre-scaled by 1/sqrt(DH)) ----
    const long long qrow = (long long)(b * SQ + q0 + wid * 16 + qr) * DM + h * DH;
    uint32_t qh[8][4], ql[8][4];
#pragma unroll
    for (int kk = 0; kk < 8; kk++) {
        float2 f[4];
        f[0] = *(const float2*)(Q + qrow + kk * 16 + qc * 2);
        f[1] = *(const float2*)(Q + qrow + 8 * DM + kk * 16 + qc * 2);
        f[2] = *(const float2*)(Q + qrow + kk * 16 + qc * 2 + 8);
        f[3] = *(const float2*)(Q + qrow + 8 * DM + kk * 16 + qc * 2 + 8);
#pragma unroll
        for (int t = 0; t < 4; t++) {
            f[t].x *= 0.08838834764831845f;
            f[t].y *= 0.08838834764831845f;
            split_h2(f[t], qh[kk][t], ql[kk][t]);
        }
    }

    float accO[16][4];
#pragma unroll
    for (int t = 0; t < 16; t++)
#pragma unroll
        for (int c = 0; c < 4; c++) accO[t][c] = 0.0f;
    float mr0 = -INFINITY, mr1 = -INFINITY, lr0 = 0.0f, lr1 = 0.0f;

    const __half* kh_g = Khi + (long long)(b * SQ) * DM + h * DH;
    const __half* kl_g = Klo + (long long)(b * SQ) * DM + h * DH;
    const __half* vh_g = Vhi + (long long)bh * DH * SQ;
    const __half* vl_g = Vlo + (long long)bh * DH * SQ;

    auto loadK = [&](int j) {
        int s0 = j * CHUNK;
        for (int g = tid; g < 1024; g += 256) {
            int r = g >> 4, c = g & 15;
            cp_async16(smb + KH_OFF + r * KROWB + c * 16, kh_g + (long long)(s0 + r) * DM + c * 8);
            cp_async16(smb + KL_OFF + r * KROWB + c * 16, kl_g + (long long)(s0 + r) * DM + c * 8);
        }
    };
    auto loadV = [&](int j) {
        int s0 = j * CHUNK;
        for (int g = tid; g < 1024; g += 256) {
            int r = g >> 3, c = g & 7;
            cp_async16(smb + VH_OFF + r * VROWB + c * 16, vh_g + (long long)r * SQ + s0 + c * 8);
            cp_async16(smb + VL_OFF + r * VROWB + c * 16, vl_g + (long long)r * SQ + s0 + c * 8);
        }
    };

    loadK(0);
    CP_COMMIT();

    const int NCH = SQ / CHUNK;   // 32
    for (int j = 0; j < NCH; j++) {
        loadV(j);
        CP_COMMIT();
        CP_WAIT1();                // K_j ready (V_j may be in flight)
        __syncthreads();

        // ---- S = Q @ K^T (3-term fp16) ----
        float accS[8][4];
#pragma unroll
        for (int t = 0; t < 8; t++)
#pragma unroll
            for (int c = 0; c < 4; c++) accS[t][c] = 0.0f;
#pragma unroll
        for (int kk = 0; kk < 8; kk++) {
#pragma unroll
            for (int t = 0; t < 8; t++) {
                uint2 bhv = *(const uint2*)(smc + KH_OFF + (8 * t + qr) * KROWB + kk * 32 + qc * 8);
                uint2 blv = *(const uint2*)(smc + KL_OFF + (8 * t + qr) * KROWB + kk * 32 + qc * 8);
                uint32_t bH[2] = {bhv.x, bhv.y}, bL[2] = {blv.x, blv.y};
                mma_f16(accS[t], ql[kk], bH);
                mma_f16(accS[t], qh[kk], bL);
                mma_f16(accS[t], qh[kk], bH);
            }
        }

        // ---- online softmax ----
        float mx0 = -INFINITY, mx1 = -INFINITY;
#pragma unroll
        for (int t = 0; t < 8; t++) {
            mx0 = fmaxf(mx0, fmaxf(accS[t][0], accS[t][1]));
            mx1 = fmaxf(mx1, fmaxf(accS[t][2], accS[t][3]));
        }
        mx0 = fmaxf(mx0, __shfl_xor_sync(0xFFFFFFFFu, mx0, 1));
        mx0 = fmaxf(mx0, __shfl_xor_sync(0xFFFFFFFFu, mx0, 2));
        mx1 = fmaxf(mx1, __shfl_xor_sync(0xFFFFFFFFu, mx1, 1));
        mx1 = fmaxf(mx1, __shfl_xor_sync(0xFFFFFFFFu, mx1, 2));
        float mn0 = fmaxf(mr0, mx0), mn1 = fmaxf(mr1, mx1);
        float al0 = __expf(mr0 - mn0), al1 = __expf(mr1 - mn1);
        mr0 = mn0; mr1 = mn1;
        lr0 *= al0; lr1 *= al1;
#pragma unroll
        for (int t = 0; t < 16; t++) {
            accO[t][0] *= al0; accO[t][1] *= al0;
            accO[t][2] *= al1; accO[t][3] *= al1;
        }
        uint32_t ph[8][2], pl[8][2];
#pragma unroll
        for (int t = 0; t < 8; t++) {
            float p0 = __expf(accS[t][0] - mn0);
            float p1 = __expf(accS[t][1] - mn0);
            float p2 = __expf(accS[t][2] - mn1);
            float p3 = __expf(accS[t][3] - mn1);
            lr0 += p0 + p1;
            lr1 += p2 + p3;
            split_h2(make_float2(p0, p1), ph[t][0], pl[t][0]);
            split_h2(make_float2(p2, p3), ph[t][1], pl[t][1]);
        }

        __syncthreads();           // all warps done reading K_j
        if (j + 1 < NCH) {
            loadK(j + 1);
            CP_COMMIT();
            CP_WAIT1();            // V_j ready (K_{j+1} in flight)
        } else {
            CP_WAIT0();            // V_j ready
        }
        __syncthreads();

        // ---- O += P @ V (3-term fp16) ----
#pragma unroll
        for (int kk2 = 0; kk2 < 4; kk2++) {
            uint32_t aH[4] = {ph[2 * kk2][0], ph[2 * kk2][1], ph[2 * kk2 + 1][0], ph[2 * kk2 + 1][1]};
            uint32_t aL[4] = {pl[2 * kk2][0], pl[2 * kk2][1], pl[2 * kk2 + 1][0], pl[2 * kk2 + 1][1]};
#pragma unroll
            for (int t = 0; t < 16; t++) {
                uint2 vh2 = *(const uint2*)(smc + VH_OFF + (8 * t + qr) * VROWB + kk2 * 32 + qc * 8);
                uint2 vl2 = *(const uint2*)(smc + VL_OFF + (8 * t + qr) * VROWB + kk2 * 32 + qc * 8);
                uint32_t bH[2] = {vh2.x, vh2.y}, bL[2] = {vl2.x, vl2.y};
                mma_f16(accO[t], aH, bL);
                mma_f16(accO[t], aL, bH);
                mma_f16(accO[t], aH, bH);
            }
        }
        __syncthreads();           // all warps done reading V_j before next loadV
    }

    // ---- epilogue: normalize and store ----
    lr0 += __shfl_xor_sync(0xFFFFFFFFu, lr0, 1);
    lr0 += __shfl_xor_sync(0xFFFFFFFFu, lr0, 2);
    lr1 += __shfl_xor_sync(0xFFFFFFFFu, lr1, 1);
    lr1 += __shfl_xor_sync(0xFFFFFFFFu, lr1, 2);
    const float i0 = 1.0f / lr0, i1 = 1.0f / lr1;
    float* crow = ctx + qrow;
#pragma unroll
    for (int t = 0; t < 16; t++) {
        *(float2*)(crow + 8 * t + qc * 2) = make_float2(accO[t][0] * i0, accO[t][1] * i0);
        *(float2*)(crow + 8 * DM + 8 * t + qc * 2) = make_float2(accO[t][2] * i1, accO[t][3] * i1);
    }
}

// ---------------- launch -------------------------------------------------------
extern "C" void kernel_launch(void* const* d_in, const int* in_sizes, int n_in,
                              void* d_out, int out_size)
{
    const float* x      = (const float*)d_in[0];
    const float* W_down = (const float*)d_in[1];
    const float* b_down = (const float*)d_in[2];
    const float* W_uk   = (const float*)d_in[3];
    const float* b_uk   = (const float*)d_in[4];
    const float* W_uv   = (const float*)d_in[5];
    const float* b_uv   = (const float*)d_in[6];
    const float* W_q    = (const float*)d_in[7];
    const float* b_q    = (const float*)d_in[8];
    const float* W_o    = (const float*)d_in[9];
    const float* b_o    = (const float*)d_in[10];
    float* out = (float*)d_out;

    void *p0, *p1, *p2, *p3, *p4, *p6, *pk0, *pk1, *pv0, *pv1;
    cudaGetSymbolAddress(&p0, g_lat);   float* lat = (float*)p0;
    cudaGetSymbolAddress(&p1, g_key);   float* key = (float*)p1;
    cudaGetSymbolAddress(&p2, g_val);   float* val = (float*)p2;
    cudaGetSymbolAddress(&p3, g_q);     float* q   = (float*)p3;
    cudaGetSymbolAddress(&p4, g_ctx);   float* ctx = (float*)p4;
    cudaGetSymbolAddress(&p6, g_wt);    float* wt  = (float*)p6;
    cudaGetSymbolAddress(&pk0, g_khi);  __half* khi = (__half*)pk0;
    cudaGetSymbolAddress(&pk1, g_klo);  __half* klo = (__half*)pk1;
    cudaGetSymbolAddress(&pv0, g_vthi); __half* vthi = (__half*)pv0;
    cudaGetSymbolAddress(&pv1, g_vtlo); __half* vtlo = (__half*)pv1;

    static bool attr_set = false;
    if (!attr_set) {
        cudaFuncSetAttribute(mma_gemm, cudaFuncAttributeMaxDynamicSharedMemorySize, SMEM_GEMM);
        cudaFuncSetAttribute(flash_kernel, cudaFuncAttributeMaxDynamicSharedMemorySize, SMEM_FLASH);
        attr_set = true;
    }

    dim3 blk(256);

    // 1) latents = x @ W_down + b_down
    transpose_kernel<<<dim3(DL/32, DM/32), dim3(32,8)>>>(W_down, wt, DL, DM);
    mma_gemm<<<dim3(DL/128, MTOT/128), blk, SMEM_GEMM>>>(x, wt, lat, b_down, DM, DM, DM, DL, 1.0f);

    // 2) keys = latents @ W_uk + b_uk
    transpose_kernel<<<dim3(DM/32, DL/32), dim3(32,8)>>>(W_uk, wt, DM, DL);
    mma_gemm<<<dim3(DM/128, MTOT/128), blk, SMEM_GEMM>>>(lat, wt, key, b_uk, DL, DL, DL, DM, 1.0f);

    // 3) values = latents @ W_uv + b_uv
    transpose_kernel<<<dim3(DM/32, DL/32), dim3(32,8)>>>(W_uv, wt, DM, DL);
    mma_gemm<<<dim3(DM/128, MTOT/128), blk, SMEM_GEMM>>>(lat, wt, val, b_uv, DL, DL, DL, DM, 1.0f);

    // 4) q = x @ W_q + b_q
    transpose_kernel<<<dim3(DM/32, DM/32), dim3(32,8)>>>(W_q, wt, DM, DM);
    mma_gemm<<<dim3(DM/128, MTOT/128), blk, SMEM_GEMM>>>(x, wt, q, b_q, DM, DM, DM, DM, 1.0f);

    // 5) pre-split K and V^T to fp16 hi/lo
    split_k_kernel<<<(MTOT * DM / 2 + 255) / 256, 256>>>(key, khi, klo);
    split_vt_kernel<<<dim3(SQ/32, DH/32, BB*NH), dim3(32,8)>>>(val, vthi, vtlo);

    // 6) fused flash attention -> ctx
    flash_kernel<<<dim3(SQ/128, BB*NH), blk, SMEM_FLASH>>>(q, khi, klo, vthi, vtlo, ctx);

    // 7) out = ctx @ W_o + b_o
    transpose_kernel<<<dim3(DM/32, DM/32), dim3(32,8)>>>(W_o, wt, DM, DM);
    mma_gemm<<<dim3(DM/128, MTOT/128), blk, SMEM_GEMM>>>(ctx, wt, out, b_o, DM, DM, DM, DM, 1.0f);
}

// round 7
// speedup vs baseline: 2.8216x; 1.1094x over previous
#include <cuda_runtime.h>
#include <cuda_fp16.h>
#include <math.h>
#include <stdint.h>

#define SQ   2048
#define DM   2048
#define DH   128
#define NH   16
#define DL   512
#define BB   4
#define MTOT (BB*SQ)

// ---------------- scratch (all pre-split operands live here) -------------------
__device__ __half g_xhi[(size_t)MTOT * DM],  g_xlo[(size_t)MTOT * DM];
__device__ __half g_lathi[(size_t)MTOT * DL], g_latlo[(size_t)MTOT * DL];
__device__ __half g_khi[(size_t)MTOT * DM],  g_klo[(size_t)MTOT * DM];
__device__ __half g_qhi[(size_t)MTOT * DM],  g_qlo[(size_t)MTOT * DM];
__device__ __half g_ctxhi[(size_t)MTOT * DM], g_ctxlo[(size_t)MTOT * DM];
__device__ float  g_val[(size_t)MTOT * DM];
__device__ __half g_vthi[(size_t)BB * NH * DH * SQ], g_vtlo[(size_t)BB * NH * DH * SQ];
__device__ __half g_wth[(size_t)DM * DM], g_wtl[(size_t)DM * DM];

// ---------------- helpers ------------------------------------------------------
__device__ __forceinline__ uint32_t smem_u32(const void* p) {
    uint32_t a;
    asm("{ .reg .u64 t; cvta.to.shared.u64 t, %1; cvt.u32.u64 %0, t; }" : "=r"(a) : "l"(p));
    return a;
}
__device__ __forceinline__ void cp_async16(uint32_t dst, const void* src) {
    asm volatile("cp.async.cg.shared.global [%0], [%1], 16;" :: "r"(dst), "l"(src) : "memory");
}
#define CP_COMMIT() asm volatile("cp.async.commit_group;" ::: "memory")
#define CP_WAIT1()  asm volatile("cp.async.wait_group 1;" ::: "memory")

__device__ __forceinline__ void split_h2(float2 f, uint32_t& hi, uint32_t& lo) {
    __half2 h = __float22half2_rn(f);
    float2 back = __half22float2(h);
    __half2 l = __float22half2_rn(make_float2(f.x - back.x, f.y - back.y));
    hi = *(uint32_t*)&h;
    lo = *(uint32_t*)&l;
}
__device__ __forceinline__ void mma_f16(float* c, const uint32_t* a, const uint32_t* b) {
    asm volatile(
        "mma.sync.aligned.m16n8k16.row.col.f32.f16.f16.f32 "
        "{%0,%1,%2,%3}, {%4,%5,%6,%7}, {%8,%9}, {%0,%1,%2,%3};"
        : "+f"(c[0]), "+f"(c[1]), "+f"(c[2]), "+f"(c[3])
        : "r"(a[0]), "r"(a[1]), "r"(a[2]), "r"(a[3]), "r"(b[0]), "r"(b[1]));
}
// permutation of k-pairs within 16-element groups: fragment pairs become contiguous
__device__ __forceinline__ int inv_pair(int p) { return ((p & 3) << 1) | (p >> 2); }

// ---------------- pre-split fp16 hi/lo GEMM: D = (A @ B^T + bias) * post -------
// A hi/lo [M][K] halves (K pair-permuted), B hi/lo [N][K] halves (permuted).
// Output: fp32 Cf and/or split Chi/Clo (permuted pairs along N for downstream use).
#define BK 32
#define AROW 80                         // bytes per smem row (64B data + 16 pad)
#define ARR (128 * AROW)                // 10240 per array
#define HSTAGE (4 * ARR)                // Ah,Al,Bh,Bl
#define SMEM_HGEMM (2 * HSTAGE)         // 81920

__global__ __launch_bounds__(256, 2)
void hgemm(const __half* __restrict__ Ah, const __half* __restrict__ Al,
           const __half* __restrict__ Bh, const __half* __restrict__ Bl,
           float* __restrict__ Cf, __half* __restrict__ Chi, __half* __restrict__ Clo,
           const float* __restrict__ bias,
           int K, int lda, int ldb, int ldc, float post)
{
    extern __shared__ char sm[];
    const uint32_t smb = smem_u32(sm);
    const int tid = threadIdx.x, wid = tid >> 5, lane = tid & 31;
    const int qr = lane >> 2, qc = lane & 3;
    const int warpM = (wid & 1) * 64, warpN = (wid >> 1) * 32;
    const int m0 = blockIdx.y * 128, n0 = blockIdx.x * 128;

    const __half* A0 = Ah + (long long)m0 * lda;
    const __half* A1 = Al + (long long)m0 * lda;
    const __half* B0 = Bh + (long long)n0 * ldb;
    const __half* B1 = Bl + (long long)n0 * ldb;

    float acc[4][4][4];
#pragma unroll
    for (int mi = 0; mi < 4; mi++)
#pragma unroll
        for (int ni = 0; ni < 4; ni++)
#pragma unroll
            for (int t = 0; t < 4; t++) acc[mi][ni][t] = 0.0f;

    auto load_stage = [&](int t, int s) {
        const int k0 = t * BK;
        uint32_t base = smb + s * HSTAGE;
#pragma unroll
        for (int j = 0; j < 2; j++) {
            int g = tid + j * 256;
            int r = g >> 2, c = g & 3;
            uint32_t off = (uint32_t)(r * AROW + c * 16);
            cp_async16(base + off,           A0 + (long long)r * lda + k0 + c * 8);
            cp_async16(base + ARR + off,     A1 + (long long)r * lda + k0 + c * 8);
            cp_async16(base + 2 * ARR + off, B0 + (long long)r * ldb + k0 + c * 8);
            cp_async16(base + 3 * ARR + off, B1 + (long long)r * ldb + k0 + c * 8);
        }
    };

    const int nk = K / BK;
    load_stage(0, 0); CP_COMMIT();
    load_stage(1, 1); CP_COMMIT();

    for (int i = 0; i < nk; i++) {
        CP_WAIT1();
        __syncthreads();
        const char* s = sm + (i & 1) * HSTAGE;
#pragma unroll
        for (int kk = 0; kk < 2; kk++) {
            uint32_t aH[4][4], aL[4][4], bH[4][2], bL[4][2];
#pragma unroll
            for (int mi = 0; mi < 4; mi++) {
                int row = warpM + mi * 16 + qr;
                uint2 v0 = *(const uint2*)(s + row * AROW + kk * 32 + qc * 8);
                uint2 v1 = *(const uint2*)(s + (row + 8) * AROW + kk * 32 + qc * 8);
                aH[mi][0] = v0.x; aH[mi][2] = v0.y; aH[mi][1] = v1.x; aH[mi][3] = v1.y;
                uint2 w0 = *(const uint2*)(s + ARR + row * AROW + kk * 32 + qc * 8);
                uint2 w1 = *(const uint2*)(s + ARR + (row + 8) * AROW + kk * 32 + qc * 8);
                aL[mi][0] = w0.x; aL[mi][2] = w0.y; aL[mi][1] = w1.x; aL[mi][3] = w1.y;
            }
#pragma unroll
            for (int ni = 0; ni < 4; ni++) {
                int col = warpN + ni * 8 + qr;
                uint2 v = *(const uint2*)(s + 2 * ARR + col * AROW + kk * 32 + qc * 8);
                bH[ni][0] = v.x; bH[ni][1] = v.y;
                uint2 w = *(const uint2*)(s + 3 * ARR + col * AROW + kk * 32 + qc * 8);
                bL[ni][0] = w.x; bL[ni][1] = w.y;
            }
#pragma unroll
            for (int mi = 0; mi < 4; mi++)
#pragma unroll
                for (int ni = 0; ni < 4; ni++) {
                    mma_f16(acc[mi][ni], aL[mi], bH[ni]);
                    mma_f16(acc[mi][ni], aH[mi], bL[ni]);
                    mma_f16(acc[mi][ni], aH[mi], bH[ni]);
                }
        }
        __syncthreads();
        if (i + 2 < nk) load_stage(i + 2, i & 1);
        CP_COMMIT();
    }

    // ---- epilogue ----
#pragma unroll
    for (int mi = 0; mi < 4; mi++) {
#pragma unroll
        for (int ni = 0; ni < 4; ni++) {
            int row = m0 + warpM + mi * 16 + qr;
            int colb = n0 + warpN + ni * 8;
            float2 bv = make_float2(0.f, 0.f);
            if (bias) bv = *(const float2*)(bias + colb + qc * 2);
            float2 v0 = make_float2((acc[mi][ni][0] + bv.x) * post, (acc[mi][ni][1] + bv.y) * post);
            float2 v1 = make_float2((acc[mi][ni][2] + bv.x) * post, (acc[mi][ni][3] + bv.y) * post);
            if (Cf) {
                *(float2*)(Cf + (long long)row * ldc + colb + qc * 2) = v0;
                *(float2*)(Cf + (long long)(row + 8) * ldc + colb + qc * 2) = v1;
            }
            if (Chi) {
                int p = (colb >> 1) + qc;
                int pp = (p & ~7) | inv_pair(p & 7);
                uint32_t h, l;
                split_h2(v0, h, l);
                ((uint32_t*)Chi)[(long long)row * (ldc >> 1) + pp] = h;
                ((uint32_t*)Clo)[(long long)row * (ldc >> 1) + pp] = l;
                split_h2(v1, h, l);
                ((uint32_t*)Chi)[(long long)(row + 8) * (ldc >> 1) + pp] = h;
                ((uint32_t*)Clo)[(long long)(row + 8) * (ldc >> 1) + pp] = l;
            }
        }
    }
}

// ---------------- transpose + split weights: W[K][N] -> Wt hi/lo [N][K] perm ---
__global__ void transpose_split(const float* __restrict__ in,
                                __half* __restrict__ hi, __half* __restrict__ lo,
                                int ldi, int ldo)
{
    __shared__ float t[32][33];
    const int c0 = blockIdx.x * 32, r0 = blockIdx.y * 32;
#pragma unroll
    for (int i = threadIdx.y; i < 32; i += 8)
        t[i][threadIdx.x] = in[(long long)(r0 + i) * ldi + c0 + threadIdx.x];
    __syncthreads();
    const int e = r0 + threadIdx.x;
    const int p = e >> 1, bo = e & 1;
    const int pe = (((p & ~7) | inv_pair(p & 7)) << 1) | bo;
#pragma unroll
    for (int i = threadIdx.y; i < 32; i += 8) {
        float v = t[threadIdx.x][i];
        __half h = __float2half_rn(v);
        __half l = __float2half_rn(v - __half2float(h));
        hi[(long long)(c0 + i) * ldo + pe] = h;
        lo[(long long)(c0 + i) * ldo + pe] = l;
    }
}

// ---------------- split x rows -> fp16 hi/lo (pair-permuted, row len DM) -------
__global__ void split_rows(const float* __restrict__ in,
                           __half* __restrict__ hi, __half* __restrict__ lo)
{
    long long i2 = (long long)blockIdx.x * blockDim.x + threadIdx.x;
    if (i2 >= (long long)MTOT * DM / 2) return;
    int d2 = (int)(i2 & (DM / 2 - 1));
    long long row = i2 >> 10;
    int d2p = (d2 & ~7) | inv_pair(d2 & 7);
    float2 v = ((const float2*)in)[i2];
    uint32_t h, l;
    split_h2(v, h, l);
    ((uint32_t*)hi)[row * (DM / 2) + d2p] = h;
    ((uint32_t*)lo)[row * (DM / 2) + d2p] = l;
}

// ---------------- split+transpose V -> V^T fp16 hi/lo (s pair-permuted) --------
__global__ void split_vt_kernel(const float* __restrict__ in,
                                __half* __restrict__ hi, __half* __restrict__ lo)
{
    __shared__ float t[32][33];
    const int bh = blockIdx.z, b = bh >> 4, h = bh & 15;
    const int s0 = blockIdx.x * 32, d0 = blockIdx.y * 32;
    const float* src = in + (long long)(b * SQ) * DM + h * DH;
#pragma unroll
    for (int i = threadIdx.y; i < 32; i += 8)
        t[i][threadIdx.x] = src[(long long)(s0 + i) * DM + d0 + threadIdx.x];
    __syncthreads();
    const int tx = threadIdx.x;
    const int r = tx & 15;
    const int sperm = (tx & 16) | (inv_pair(r >> 1) * 2 + (r & 1));
#pragma unroll
    for (int i = threadIdx.y; i < 32; i += 8) {
        float v = t[tx][i];
        __half hv = __float2half_rn(v);
        __half lv = __float2half_rn(v - __half2float(hv));
        long long off = ((long long)bh * DH + d0 + i) * SQ + s0 + sperm;
        hi[off] = hv;
        lo[off] = lv;
    }
}

// ---------------- fused flash attention (double-buffered K+V) ------------------
#define CHUNK 64
#define KROWB 272
#define VROWB 144
#define FSTG  71680                      // KH 17408 + KL 17408 + VH 18432 + VL 18432
#define FKH(s) ((s) * FSTG + 0)
#define FKL(s) ((s) * FSTG + 17408)
#define FVH(s) ((s) * FSTG + 34816)
#define FVL(s) ((s) * FSTG + 53248)
#define SMEM_FLASH (2 * FSTG)            // 143360

__global__ __launch_bounds__(256)
void flash_kernel(const __half* __restrict__ Qhi, const __half* __restrict__ Qlo,
                  const __half* __restrict__ Khi, const __half* __restrict__ Klo,
                  const __half* __restrict__ Vhi, const __half* __restrict__ Vlo,
                  __half* __restrict__ Chi, __half* __restrict__ Clo)
{
    extern __shared__ char smc[];
    const uint32_t smb = smem_u32(smc);
    const int tid = threadIdx.x, wid = tid >> 5, lane = tid & 31;
    const int qr = lane >> 2, qc = lane & 3;
    const int bh = blockIdx.y, b = bh >> 4, h = bh & 15;
    const int q0 = blockIdx.x * 128;

    // ---- Q fragments from pre-split gmem (already scaled by 1/sqrt(DH)) ----
    const long long rowA = (long long)(b * SQ + q0 + wid * 16 + qr);
    const long long qoff = rowA * DM + h * DH;
    uint32_t qh[8][4], ql[8][4];
#pragma unroll
    for (int kk = 0; kk < 8; kk++) {
        uint2 v0 = *(const uint2*)(Qhi + qoff + kk * 16 + qc * 4);
        uint2 v1 = *(const uint2*)(Qhi + qoff + 8 * DM + kk * 16 + qc * 4);
        qh[kk][0] = v0.x; qh[kk][2] = v0.y; qh[kk][1] = v1.x; qh[kk][3] = v1.y;
        uint2 w0 = *(const uint2*)(Qlo + qoff + kk * 16 + qc * 4);
        uint2 w1 = *(const uint2*)(Qlo + qoff + 8 * DM + kk * 16 + qc * 4);
        ql[kk][0] = w0.x; ql[kk][2] = w0.y; ql[kk][1] = w1.x; ql[kk][3] = w1.y;
    }

    float accO[16][4];
#pragma unroll
    for (int t = 0; t < 16; t++)
#pragma unroll
        for (int c = 0; c < 4; c++) accO[t][c] = 0.0f;
    float mr0 = -INFINITY, mr1 = -INFINITY, lr0 = 0.0f, lr1 = 0.0f;

    const __half* kh_g = Khi + (long long)(b * SQ) * DM + h * DH;
    const __half* kl_g = Klo + (long long)(b * SQ) * DM + h * DH;
    const __half* vh_g = Vhi + (long long)bh * DH * SQ;
    const __half* vl_g = Vlo + (long long)bh * DH * SQ;

    auto loadKV = [&](int j, int s) {
        int s0 = j * CHUNK;
        for (int g = tid; g < 1024; g += 256) {
            int r = g >> 4, c = g & 15;
            cp_async16(smb + FKH(s) + r * KROWB + c * 16, kh_g + (long long)(s0 + r) * DM + c * 8);
            cp_async16(smb + FKL(s) + r * KROWB + c * 16, kl_g + (long long)(s0 + r) * DM + c * 8);
        }
        for (int g = tid; g < 1024; g += 256) {
            int r = g >> 3, c = g & 7;
            cp_async16(smb + FVH(s) + r * VROWB + c * 16, vh_g + (long long)r * SQ + s0 + c * 8);
            cp_async16(smb + FVL(s) + r * VROWB + c * 16, vl_g + (long long)r * SQ + s0 + c * 8);
        }
    };

    loadKV(0, 0);
    CP_COMMIT();

    const int NCH = SQ / CHUNK;   // 32
    for (int j = 0; j < NCH; j++) {
        if (j + 1 < NCH) loadKV(j + 1, (j + 1) & 1);
        CP_COMMIT();
        CP_WAIT1();                // chunk j complete; j+1 in flight
        __syncthreads();
        const int st = j & 1;

        // ---- S = Q @ K^T ----
        float accS[8][4];
#pragma unroll
        for (int t = 0; t < 8; t++)
#pragma unroll
            for (int c = 0; c < 4; c++) accS[t][c] = 0.0f;
#pragma unroll
        for (int kk = 0; kk < 8; kk++) {
#pragma unroll
            for (int t = 0; t < 8; t++) {
                uint2 bhv = *(const uint2*)(smc + FKH(st) + (8 * t + qr) * KROWB + kk * 32 + qc * 8);
                uint2 blv = *(const uint2*)(smc + FKL(st) + (8 * t + qr) * KROWB + kk * 32 + qc * 8);
                uint32_t bH[2] = {bhv.x, bhv.y}, bL[2] = {blv.x, blv.y};
                mma_f16(accS[t], ql[kk], bH);
                mma_f16(accS[t], qh[kk], bL);
                mma_f16(accS[t], qh[kk], bH);
            }
        }

        // ---- online softmax ----
        float mx0 = -INFINITY, mx1 = -INFINITY;
#pragma unroll
        for (int t = 0; t < 8; t++) {
            mx0 = fmaxf(mx0, fmaxf(accS[t][0], accS[t][1]));
            mx1 = fmaxf(mx1, fmaxf(accS[t][2], accS[t][3]));
        }
        mx0 = fmaxf(mx0, __shfl_xor_sync(0xFFFFFFFFu, mx0, 1));
        mx0 = fmaxf(mx0, __shfl_xor_sync(0xFFFFFFFFu, mx0, 2));
        mx1 = fmaxf(mx1, __shfl_xor_sync(0xFFFFFFFFu, mx1, 1));
        mx1 = fmaxf(mx1, __shfl_xor_sync(0xFFFFFFFFu, mx1, 2));
        float mn0 = fmaxf(mr0, mx0), mn1 = fmaxf(mr1, mx1);
        float al0 = __expf(mr0 - mn0), al1 = __expf(mr1 - mn1);
        mr0 = mn0; mr1 = mn1;
        lr0 *= al0; lr1 *= al1;
#pragma unroll
        for (int t = 0; t < 16; t++) {
            accO[t][0] *= al0; accO[t][1] *= al0;
            accO[t][2] *= al1; accO[t][3] *= al1;
        }
        uint32_t ph[8][2], pl[8][2];
#pragma unroll
        for (int t = 0; t < 8; t++) {
            float p0 = __expf(accS[t][0] - mn0);
            float p1 = __expf(accS[t][1] - mn0);
            float p2 = __expf(accS[t][2] - mn1);
            float p3 = __expf(accS[t][3] - mn1);
            lr0 += p0 + p1;
            lr1 += p2 + p3;
            split_h2(make_float2(p0, p1), ph[t][0], pl[t][0]);
            split_h2(make_float2(p2, p3), ph[t][1], pl[t][1]);
        }

        // ---- O += P @ V ----
#pragma unroll
        for (int kk2 = 0; kk2 < 4; kk2++) {
            uint32_t aH[4] = {ph[2 * kk2][0], ph[2 * kk2][1], ph[2 * kk2 + 1][0], ph[2 * kk2 + 1][1]};
            uint32_t aL[4] = {pl[2 * kk2][0], pl[2 * kk2][1], pl[2 * kk2 + 1][0], pl[2 * kk2 + 1][1]};
#pragma unroll
            for (int t = 0; t < 16; t++) {
                uint2 vh2 = *(const uint2*)(smc + FVH(st) + (8 * t + qr) * VROWB + kk2 * 32 + qc * 8);
                uint2 vl2 = *(const uint2*)(smc + FVL(st) + (8 * t + qr) * VROWB + kk2 * 32 + qc * 8);
                uint32_t bH[2] = {vh2.x, vh2.y}, bL[2] = {vl2.x, vl2.y};
                mma_f16(accO[t], aH, bL);
                mma_f16(accO[t], aL, bH);
                mma_f16(accO[t], aH, bH);
            }
        }
        __syncthreads();           // buffer free for next-next chunk's loads
    }

    // ---- epilogue: normalize, split, store ----
    lr0 += __shfl_xor_sync(0xFFFFFFFFu, lr0, 1);
    lr0 += __shfl_xor_sync(0xFFFFFFFFu, lr0, 2);
    lr1 += __shfl_xor_sync(0xFFFFFFFFu, lr1, 1);
    lr1 += __shfl_xor_sync(0xFFFFFFFFu, lr1, 2);
    const float i0 = 1.0f / lr0, i1 = 1.0f / lr1;
#pragma unroll
    for (int t = 0; t < 16; t++) {
        int p = 64 * h + 4 * t + qc;
        int pp = (p & ~7) | inv_pair(p & 7);
        uint32_t hh, ll;
        split_h2(make_float2(accO[t][0] * i0, accO[t][1] * i0), hh, ll);
        ((uint32_t*)Chi)[rowA * (DM / 2) + pp] = hh;
        ((uint32_t*)Clo)[rowA * (DM / 2) + pp] = ll;
        split_h2(make_float2(accO[t][2] * i1, accO[t][3] * i1), hh, ll);
        ((uint32_t*)Chi)[(rowA + 8) * (DM / 2) + pp] = hh;
        ((uint32_t*)Clo)[(rowA + 8) * (DM / 2) + pp] = ll;
    }
}

// ---------------- launch -------------------------------------------------------
extern "C" void kernel_launch(void* const* d_in, const int* in_sizes, int n_in,
                              void* d_out, int out_size)
{
    const float* x      = (const float*)d_in[0];
    const float* W_down = (const float*)d_in[1];
    const float* b_down = (const float*)d_in[2];
    const float* W_uk   = (const float*)d_in[3];
    const float* b_uk   = (const float*)d_in[4];
    const float* W_uv   = (const float*)d_in[5];
    const float* b_uv   = (const float*)d_in[6];
    const float* W_q    = (const float*)d_in[7];
    const float* b_q    = (const float*)d_in[8];
    const float* W_o    = (const float*)d_in[9];
    const float* b_o    = (const float*)d_in[10];
    float* out = (float*)d_out;

    void *pa, *pb;
    cudaGetSymbolAddress(&pa, g_xhi);   __half* xhi = (__half*)pa;
    cudaGetSymbolAddress(&pa, g_xlo);   __half* xlo = (__half*)pa;
    cudaGetSymbolAddress(&pa, g_lathi); __half* lathi = (__half*)pa;
    cudaGetSymbolAddress(&pa, g_latlo); __half* latlo = (__half*)pa;
    cudaGetSymbolAddress(&pa, g_khi);   __half* khi = (__half*)pa;
    cudaGetSymbolAddress(&pa, g_klo);   __half* klo = (__half*)pa;
    cudaGetSymbolAddress(&pa, g_qhi);   __half* qhi = (__half*)pa;
    cudaGetSymbolAddress(&pa, g_qlo);   __half* qlo = (__half*)pa;
    cudaGetSymbolAddress(&pa, g_ctxhi); __half* ctxhi = (__half*)pa;
    cudaGetSymbolAddress(&pa, g_ctxlo); __half* ctxlo = (__half*)pa;
    cudaGetSymbolAddress(&pa, g_val);   float* val = (float*)pa;
    cudaGetSymbolAddress(&pa, g_vthi);  __half* vthi = (__half*)pa;
    cudaGetSymbolAddress(&pa, g_vtlo);  __half* vtlo = (__half*)pa;
    cudaGetSymbolAddress(&pa, g_wth);   __half* wth = (__half*)pa;
    cudaGetSymbolAddress(&pb, g_wtl);   __half* wtl = (__half*)pb;

    static bool attr_set = false;
    if (!attr_set) {
        cudaFuncSetAttribute(hgemm, cudaFuncAttributeMaxDynamicSharedMemorySize, SMEM_HGEMM);
        cudaFuncSetAttribute(flash_kernel, cudaFuncAttributeMaxDynamicSharedMemorySize, SMEM_FLASH);
        attr_set = true;
    }

    const float inv_sqrt_dh = 0.08838834764831845f;
    dim3 blk(256);

    // 0) split x -> fp16 hi/lo (pair-permuted)
    split_rows<<<(int)((MTOT * (long long)DM / 2 + 255) / 256), 256>>>(x, xhi, xlo);

    // 1) latents = x @ W_down + b_down  -> split lat
    transpose_split<<<dim3(DL/32, DM/32), dim3(32,8)>>>(W_down, wth, wtl, DL, DM);
    hgemm<<<dim3(DL/128, MTOT/128), blk, SMEM_HGEMM>>>(
        xhi, xlo, wth, wtl, nullptr, lathi, latlo, b_down, DM, DM, DM, DL, 1.0f);

    // 2) keys = lat @ W_uk + b_uk  -> split K
    transpose_split<<<dim3(DM/32, DL/32), dim3(32,8)>>>(W_uk, wth, wtl, DM, DL);
    hgemm<<<dim3(DM/128, MTOT/128), blk, SMEM_HGEMM>>>(
        lathi, latlo, wth, wtl, nullptr, khi, klo, b_uk, DL, DL, DL, DM, 1.0f);

    // 3) values = lat @ W_uv + b_uv  -> fp32 val
    transpose_split<<<dim3(DM/32, DL/32), dim3(32,8)>>>(W_uv, wth, wtl, DM, DL);
    hgemm<<<dim3(DM/128, MTOT/128), blk, SMEM_HGEMM>>>(
        lathi, latlo, wth, wtl, val, nullptr, nullptr, b_uv, DL, DL, DL, DM, 1.0f);

    // 4) q = (x @ W_q + b_q) / sqrt(DH)  -> split Q
    transpose_split<<<dim3(DM/32, DM/32), dim3(32,8)>>>(W_q, wth, wtl, DM, DM);
    hgemm<<<dim3(DM/128, MTOT/128), blk, SMEM_HGEMM>>>(
        xhi, xlo, wth, wtl, nullptr, qhi, qlo, b_q, DM, DM, DM, DM, inv_sqrt_dh);

    // 5) split+transpose V
    split_vt_kernel<<<dim3(SQ/32, DH/32, BB*NH), dim3(32,8)>>>(val, vthi, vtlo);

    // 6) flash attention -> split ctx
    flash_kernel<<<dim3(SQ/128, BB*NH), blk, SMEM_FLASH>>>(
        qhi, qlo, khi, klo, vthi, vtlo, ctxhi, ctxlo);

    // 7) out = ctx @ W_o + b_o
    transpose_split<<<dim3(DM/32, DM/32), dim3(32,8)>>>(W_o, wth, wtl, DM, DM);
    hgemm<<<dim3(DM/128, MTOT/128), blk, SMEM_HGEMM>>>(
        ctxhi, ctxlo, wth, wtl, out, nullptr, nullptr, b_o, DM, DM, DM, DM, 1.0f);
}